// round 1
// baseline (speedup 1.0000x reference)
#include <cuda_runtime.h>
#include <cuda_bf16.h>
#include <cstdint>

// ---------------------------------------------------------------------------
// GRUModel: x(512,2,1024) -> transpose -> 4-layer GRU(H=128) over T=512,
// batch N=1024 -- BUT the head reads h[:, -1, :] == batch element 1023 only.
// Batch elements are independent in a GRU, so we compute ONLY n=1023:
//   batch-1 GRU, T=512, H=128, 4 layers, then per-t FC(128->128 relu ->3).
// Output: (512, 3) float32.
// ---------------------------------------------------------------------------

#define T_STEPS 512
#define HID 128
#define G3   384   // 3*HID

// scratch (no allocations allowed)
__device__ float g_G[T_STEPS * G3];    // gi for the layer currently recurring
__device__ float g_H[T_STEPS * HID];   // per-t hidden output of current layer

static __device__ __forceinline__ float fast_sigmoid(float x) {
    return __fdividef(1.0f, 1.0f + __expf(-x));
}
static __device__ __forceinline__ float fast_tanh(float x) {
    // (e^{2x}-1)/(e^{2x}+1); overflow of e -> returns +1 (correct limit)
    float e = __expf(2.0f * x);
    return 1.0f - __fdividef(2.0f, e + 1.0f);
}
static __device__ __forceinline__ float f32x2_lo(unsigned long long v) {
    return __uint_as_float((unsigned int)(v & 0xffffffffu));
}
static __device__ __forceinline__ float f32x2_hi(unsigned long long v) {
    return __uint_as_float((unsigned int)(v >> 32));
}

// ---------------------------------------------------------------------------
// gi for layer 0:  G[t][g] = W_ih0[g][0]*x[t,0,1023] + W_ih0[g][1]*x[t,1,1023] + b_ih0[g]
// grid=(512), block=(384)
// ---------------------------------------------------------------------------
__global__ void gi0_kernel(const float* __restrict__ x,
                           const float* __restrict__ W_ih0,
                           const float* __restrict__ b_ih0) {
    int t = blockIdx.x;
    int j = threadIdx.x;
    float x0 = x[t * 2048 + 1023];          // x[t,0,1023]
    float x1 = x[t * 2048 + 1024 + 1023];   // x[t,1,1023]
    g_G[t * G3 + j] = fmaf(W_ih0[j * 2], x0, fmaf(W_ih0[j * 2 + 1], x1, b_ih0[j]));
}

// ---------------------------------------------------------------------------
// gi for layers 1..3:  G[t][g] = b_ih[g] + sum_k W_ih[g][k] * H[t][k]
// grid=(512), block=(384). Fully parallel across t.
// ---------------------------------------------------------------------------
__global__ void gi_kernel(const float* __restrict__ W_ih,
                          const float* __restrict__ b_ih) {
    __shared__ __align__(16) float sh[HID];
    int t = blockIdx.x;
    int j = threadIdx.x;
    if (j < HID) sh[j] = g_H[t * HID + j];
    __syncthreads();
    const float4* wr = reinterpret_cast<const float4*>(W_ih + j * HID);
    const float4* hv = reinterpret_cast<const float4*>(sh);
    float a0 = 0.f, a1 = 0.f, a2 = 0.f, a3 = 0.f;
#pragma unroll
    for (int kk = 0; kk < HID / 4; kk++) {
        float4 w = wr[kk];
        float4 h = hv[kk];
        a0 = fmaf(w.x, h.x, a0);
        a1 = fmaf(w.y, h.y, a1);
        a2 = fmaf(w.z, h.z, a2);
        a3 = fmaf(w.w, h.w, a3);
    }
    g_G[t * G3 + j] = (a0 + a1) + (a2 + a3) + b_ih[j];
}

// ---------------------------------------------------------------------------
// Recurrent core for one layer. Single block, 384 threads, one CTA on one SM.
// Thread j owns row j of W_hh (128 weights, held in registers as 64 f32x2).
// Per step: gh = W_hh @ h + b_hh via packed fma.rn.f32x2 (2 MACs/instr),
// then threads 0..127 do the gate math and update h in smem.
// ---------------------------------------------------------------------------
__global__ void __launch_bounds__(G3, 1)
rec_kernel(const float* __restrict__ W_hh,   // [384,128] this layer
           const float* __restrict__ b_hh,   // [384]     this layer
           int store_all)                    // always 1 here (kept for clarity)
{
    __shared__ __align__(16) float sh_h[HID];
    __shared__ float sh_gh[G3];
    __shared__ float sh_gi[G3];

    const int j = threadIdx.x;

    // --- load this row's weights into registers as packed f32x2 ---
    unsigned long long w[64];
    {
        const ulonglong2* wrow = reinterpret_cast<const ulonglong2*>(W_hh + j * HID);
#pragma unroll
        for (int kk = 0; kk < 32; kk++) {
            ulonglong2 v = wrow[kk];
            w[2 * kk]     = v.x;
            w[2 * kk + 1] = v.y;
        }
    }
    const float bh = b_hh[j];

    if (j < HID) sh_h[j] = 0.0f;
    __syncthreads();

    for (int t = 0; t < T_STEPS; t++) {
        // prefetch gi (needed only after the matvec; latency hidden)
        float giv = g_G[t * G3 + j];

        unsigned long long a0 = 0ull, a1 = 0ull, a2 = 0ull, a3 = 0ull;
        const ulonglong2* h2 = reinterpret_cast<const ulonglong2*>(sh_h);
#pragma unroll
        for (int kk = 0; kk < 16; kk++) {
            ulonglong2 hv0 = h2[2 * kk];
            ulonglong2 hv1 = h2[2 * kk + 1];
            asm("fma.rn.f32x2 %0, %1, %2, %0;" : "+l"(a0) : "l"(w[4 * kk + 0]), "l"(hv0.x));
            asm("fma.rn.f32x2 %0, %1, %2, %0;" : "+l"(a1) : "l"(w[4 * kk + 1]), "l"(hv0.y));
            asm("fma.rn.f32x2 %0, %1, %2, %0;" : "+l"(a2) : "l"(w[4 * kk + 2]), "l"(hv1.x));
            asm("fma.rn.f32x2 %0, %1, %2, %0;" : "+l"(a3) : "l"(w[4 * kk + 3]), "l"(hv1.y));
        }
        float s = ((f32x2_lo(a0) + f32x2_hi(a0)) + (f32x2_lo(a1) + f32x2_hi(a1)))
                + ((f32x2_lo(a2) + f32x2_hi(a2)) + (f32x2_lo(a3) + f32x2_hi(a3)));
        sh_gh[j] = s + bh;
        sh_gi[j] = giv;
        __syncthreads();

        if (j < HID) {
            float ghr = sh_gh[j];
            float ghz = sh_gh[j + HID];
            float ghn = sh_gh[j + 2 * HID];
            float gir = sh_gi[j];
            float giz = sh_gi[j + HID];
            float gin = sh_gi[j + 2 * HID];
            float r = fast_sigmoid(gir + ghr);
            float z = fast_sigmoid(giz + ghz);
            float n = fast_tanh(fmaf(r, ghn, gin));
            float hprev = sh_h[j];
            float hnew = fmaf(z, hprev - n, n);   // (1-z)*n + z*h
            sh_h[j] = hnew;
            g_H[t * HID + j] = hnew;
        }
        __syncthreads();
    }
    (void)store_all;
}

// ---------------------------------------------------------------------------
// Head:  out[t] = relu(h3[t] @ fc1^T + b1) @ fc2^T + b2    grid=(512), block=(128)
// ---------------------------------------------------------------------------
__global__ void fc_kernel(const float* __restrict__ fc1_w,
                          const float* __restrict__ fc1_b,
                          const float* __restrict__ fc2_w,
                          const float* __restrict__ fc2_b,
                          float* __restrict__ out) {
    __shared__ __align__(16) float sh[HID];
    __shared__ float hid[HID];
    int t = blockIdx.x;
    int i = threadIdx.x;
    sh[i] = g_H[t * HID + i];
    __syncthreads();
    const float4* wr = reinterpret_cast<const float4*>(fc1_w + i * HID);
    const float4* hv = reinterpret_cast<const float4*>(sh);
    float a0 = 0.f, a1 = 0.f, a2 = 0.f, a3 = 0.f;
#pragma unroll
    for (int kk = 0; kk < HID / 4; kk++) {
        float4 w = wr[kk];
        float4 h = hv[kk];
        a0 = fmaf(w.x, h.x, a0);
        a1 = fmaf(w.y, h.y, a1);
        a2 = fmaf(w.z, h.z, a2);
        a3 = fmaf(w.w, h.w, a3);
    }
    hid[i] = fmaxf((a0 + a1) + (a2 + a3) + fc1_b[i], 0.0f);
    __syncthreads();
    if (i < 3) {
        float acc = fc2_b[i];
#pragma unroll 8
        for (int k = 0; k < HID; k++) acc = fmaf(fc2_w[i * HID + k], hid[k], acc);
        out[t * 3 + i] = acc;
    }
}

// ---------------------------------------------------------------------------
extern "C" void kernel_launch(void* const* d_in, const int* in_sizes, int n_in,
                              void* d_out, int out_size) {
    const float* x         = (const float*)d_in[0];  // (512,2,1024)
    const float* W_ih0     = (const float*)d_in[1];  // (384,2)
    const float* W_ih_rest = (const float*)d_in[2];  // (3,384,128)
    const float* W_hh      = (const float*)d_in[3];  // (4,384,128)
    const float* b_ih      = (const float*)d_in[4];  // (4,384)
    const float* b_hh      = (const float*)d_in[5];  // (4,384)
    const float* fc1_w     = (const float*)d_in[6];  // (128,128)
    const float* fc1_b     = (const float*)d_in[7];  // (128)
    const float* fc2_w     = (const float*)d_in[8];  // (3,128)
    const float* fc2_b     = (const float*)d_in[9];  // (3)
    float* out = (float*)d_out;                      // (512,3)
    (void)in_sizes; (void)n_in; (void)out_size;

    // layer 0
    gi0_kernel<<<T_STEPS, G3>>>(x, W_ih0, b_ih);
    rec_kernel<<<1, G3>>>(W_hh, b_hh, 1);
    // layers 1..3
    for (int l = 1; l < 4; l++) {
        gi_kernel<<<T_STEPS, G3>>>(W_ih_rest + (size_t)(l - 1) * G3 * HID,
                                   b_ih + (size_t)l * G3);
        rec_kernel<<<1, G3>>>(W_hh + (size_t)l * G3 * HID,
                              b_hh + (size_t)l * G3, 1);
    }
    // head
    fc_kernel<<<T_STEPS, HID>>>(fc1_w, fc1_b, fc2_w, fc2_b, out);
}

// round 2
// speedup vs baseline: 1.8171x; 1.8171x over previous
#include <cuda_runtime.h>
#include <cuda_bf16.h>
#include <cstdint>

// ---------------------------------------------------------------------------
// GRUModel: only batch element 1023 matters (head reads h[:, -1, :]).
// Batch-1 GRU, T=512, H=128, 4 layers, FC head per t.
//
// This round: wavefront pipeline. 7 persistent CTAs run concurrently:
//   CTA 0: rec layer 0 (inline 2-wide gi from x)
//   CTA 1/3/5: gi matvec for layers 1/2/3 (W_ih in registers)
//   CTA 2/4/6: rec for layers 1/2/3 (W_hh in registers)
// Handoff through L2 with acquire/release flags; poll overlapped with gates.
// ---------------------------------------------------------------------------

#define T_STEPS 512
#define HID 128
#define G3   384   // 3*HID

__device__ float g_H[4 * T_STEPS * HID];    // h per layer per t
__device__ float g_GI[3 * T_STEPS * G3];    // gi for layers 1..3
__device__ int   f_h[4 * T_STEPS];          // h-ready flags
__device__ int   f_gi[4 * T_STEPS];         // gi-ready flags (rows 1..3 used)

static __device__ __forceinline__ float fast_sigmoid(float x) {
    return __fdividef(1.0f, 1.0f + __expf(-x));
}
static __device__ __forceinline__ float fast_tanh(float x) {
    float e = __expf(2.0f * x);
    return 1.0f - __fdividef(2.0f, e + 1.0f);
}
static __device__ __forceinline__ float f32x2_lo(unsigned long long v) {
    return __uint_as_float((unsigned int)(v & 0xffffffffu));
}
static __device__ __forceinline__ float f32x2_hi(unsigned long long v) {
    return __uint_as_float((unsigned int)(v >> 32));
}
static __device__ __forceinline__ void st_release(int* p, int v) {
    asm volatile("st.release.gpu.global.s32 [%0], %1;" :: "l"(p), "r"(v) : "memory");
}
static __device__ __forceinline__ int ld_acquire(const int* p) {
    int v;
    asm volatile("ld.acquire.gpu.global.s32 %0, [%1];" : "=r"(v) : "l"(p) : "memory");
    return v;
}
static __device__ __forceinline__ void spin_until(const int* p) {
    while (ld_acquire(p) == 0) { }
}

// 128-wide dot product: thread-owned packed weights vs broadcast smem vector.
static __device__ __forceinline__ float dot128(const unsigned long long* w,
                                               const float* sh_vec) {
    unsigned long long a0 = 0ull, a1 = 0ull, a2 = 0ull, a3 = 0ull;
    const ulonglong2* h2 = reinterpret_cast<const ulonglong2*>(sh_vec);
#pragma unroll
    for (int kk = 0; kk < 16; kk++) {
        ulonglong2 hv0 = h2[2 * kk];
        ulonglong2 hv1 = h2[2 * kk + 1];
        asm("fma.rn.f32x2 %0, %1, %2, %0;" : "+l"(a0) : "l"(w[4 * kk + 0]), "l"(hv0.x));
        asm("fma.rn.f32x2 %0, %1, %2, %0;" : "+l"(a1) : "l"(w[4 * kk + 1]), "l"(hv0.y));
        asm("fma.rn.f32x2 %0, %1, %2, %0;" : "+l"(a2) : "l"(w[4 * kk + 2]), "l"(hv1.x));
        asm("fma.rn.f32x2 %0, %1, %2, %0;" : "+l"(a3) : "l"(w[4 * kk + 3]), "l"(hv1.y));
    }
    return ((f32x2_lo(a0) + f32x2_hi(a0)) + (f32x2_lo(a1) + f32x2_hi(a1)))
         + ((f32x2_lo(a2) + f32x2_hi(a2)) + (f32x2_lo(a3) + f32x2_hi(a3)));
}

static __device__ __forceinline__ void load_row128(unsigned long long* w,
                                                   const float* row) {
    const ulonglong2* wr = reinterpret_cast<const ulonglong2*>(row);
#pragma unroll
    for (int kk = 0; kk < 32; kk++) {
        ulonglong2 v = wr[kk];
        w[2 * kk]     = v.x;
        w[2 * kk + 1] = v.y;
    }
}

__global__ void reset_flags_kernel() {
    int i = blockIdx.x * blockDim.x + threadIdx.x;
    if (i < 4 * T_STEPS) { f_h[i] = 0; f_gi[i] = 0; }
}

// ---------------------------------------------------------------------------
// Persistent pipeline kernel: 7 CTAs, 384 threads each.
// ---------------------------------------------------------------------------
__global__ void __launch_bounds__(G3, 1)
pipeline_kernel(const float* __restrict__ x,         // (512,2,1024)
                const float* __restrict__ W_ih0,     // (384,2)
                const float* __restrict__ W_ih_rest, // (3,384,128)
                const float* __restrict__ W_hh,      // (4,384,128)
                const float* __restrict__ b_ih,      // (4,384)
                const float* __restrict__ b_hh)      // (4,384)
{
    const int role = blockIdx.x;       // 0:rec0 1:gi1 2:rec1 3:gi2 4:rec2 5:gi3 6:rec3
    const int j = threadIdx.x;

    if (role & 1) {
        // ---------------- gi CTA for layer l = (role+1)/2  (1..3) ----------
        const int l = (role + 1) >> 1;
        __shared__ __align__(16) float sh_h[HID];

        unsigned long long w[64];
        load_row128(w, W_ih_rest + ((size_t)(l - 1) * G3 + j) * HID);
        const float bi = b_ih[l * G3 + j];
        float* gi_out = g_GI + (size_t)(l - 1) * T_STEPS * G3;
        const float* h_in = g_H + (size_t)(l - 1) * T_STEPS * HID;

        for (int t = 0; t < T_STEPS; t++) {
            if (j == 0) spin_until(&f_h[(l - 1) * T_STEPS + t]);
            __syncthreads();
            if (j < 32) {
                reinterpret_cast<float4*>(sh_h)[j] =
                    reinterpret_cast<const float4*>(h_in + t * HID)[j];
            }
            __syncthreads();
            float s = dot128(w, sh_h) + bi;
            gi_out[t * G3 + j] = s;
            __syncthreads();
            if (j == 0) st_release(&f_gi[l * T_STEPS + t], 1);
        }
    } else {
        // ---------------- rec CTA for layer l = role/2 ----------------------
        const int l = role >> 1;
        __shared__ __align__(16) float sh_h[HID];
        __shared__ float sh_gh[G3];
        __shared__ float sh_gi[G3];

        unsigned long long w[64];
        load_row128(w, W_hh + ((size_t)l * G3 + j) * HID);
        const float bh = b_hh[l * G3 + j];

        // layer-0 inline gi coefficients
        float w0 = 0.f, w1 = 0.f, bi0 = 0.f;
        if (l == 0) {
            w0 = W_ih0[j * 2];
            w1 = W_ih0[j * 2 + 1];
            bi0 = b_ih[j];
        }
        const float* gi_in = (l > 0) ? (g_GI + (size_t)(l - 1) * T_STEPS * G3) : nullptr;
        float* h_out = g_H + (size_t)l * T_STEPS * HID;

        if (j < HID) sh_h[j] = 0.0f;
        if (l > 0 && j == 383) spin_until(&f_gi[l * T_STEPS + 0]);
        __syncthreads();

        for (int t = 0; t < T_STEPS; t++) {
            float giv;
            if (l == 0) {
                float x0 = __ldg(x + (size_t)t * 2048 + 1023);
                float x1 = __ldg(x + (size_t)t * 2048 + 2047);
                giv = fmaf(w0, x0, fmaf(w1, x1, bi0));
            } else {
                giv = gi_in[t * G3 + j];   // ready: flag acquired last iter
            }
            float s = dot128(w, sh_h);
            sh_gh[j] = s + bh;
            sh_gi[j] = giv;
            __syncthreads();

            if (j < HID) {
                float ghr = sh_gh[j];
                float ghz = sh_gh[j + HID];
                float ghn = sh_gh[j + 2 * HID];
                float r = fast_sigmoid(sh_gi[j] + ghr);
                float z = fast_sigmoid(sh_gi[j + HID] + ghz);
                float n = fast_tanh(fmaf(r, ghn, sh_gi[j + 2 * HID]));
                float hnew = fmaf(z, sh_h[j] - n, n);   // (1-z)*n + z*h
                sh_h[j] = hnew;
                h_out[t * HID + j] = hnew;
            } else if (j == 383 && l > 0 && t + 1 < T_STEPS) {
                spin_until(&f_gi[l * T_STEPS + t + 1]);   // overlap with gates
            }
            __syncthreads();
            if (j == 0) st_release(&f_h[l * T_STEPS + t], 1);
        }
    }
}

// ---------------------------------------------------------------------------
// Head:  out[t] = relu(h3[t] @ fc1^T + b1) @ fc2^T + b2   grid=(512), block=(128)
// ---------------------------------------------------------------------------
__global__ void fc_kernel(const float* __restrict__ fc1_w,
                          const float* __restrict__ fc1_b,
                          const float* __restrict__ fc2_w,
                          const float* __restrict__ fc2_b,
                          float* __restrict__ out) {
    __shared__ __align__(16) float sh[HID];
    __shared__ float hid[HID];
    int t = blockIdx.x;
    int i = threadIdx.x;
    sh[i] = g_H[(size_t)3 * T_STEPS * HID + t * HID + i];
    __syncthreads();
    const float4* wr = reinterpret_cast<const float4*>(fc1_w + i * HID);
    const float4* hv = reinterpret_cast<const float4*>(sh);
    float a0 = 0.f, a1 = 0.f, a2 = 0.f, a3 = 0.f;
#pragma unroll
    for (int kk = 0; kk < HID / 4; kk++) {
        float4 w = wr[kk];
        float4 h = hv[kk];
        a0 = fmaf(w.x, h.x, a0);
        a1 = fmaf(w.y, h.y, a1);
        a2 = fmaf(w.z, h.z, a2);
        a3 = fmaf(w.w, h.w, a3);
    }
    hid[i] = fmaxf((a0 + a1) + (a2 + a3) + fc1_b[i], 0.0f);
    __syncthreads();
    if (i < 3) {
        float acc = fc2_b[i];
#pragma unroll 8
        for (int k = 0; k < HID; k++) acc = fmaf(fc2_w[i * HID + k], hid[k], acc);
        out[t * 3 + i] = acc;
    }
}

// ---------------------------------------------------------------------------
extern "C" void kernel_launch(void* const* d_in, const int* in_sizes, int n_in,
                              void* d_out, int out_size) {
    const float* x         = (const float*)d_in[0];
    const float* W_ih0     = (const float*)d_in[1];
    const float* W_ih_rest = (const float*)d_in[2];
    const float* W_hh      = (const float*)d_in[3];
    const float* b_ih      = (const float*)d_in[4];
    const float* b_hh      = (const float*)d_in[5];
    const float* fc1_w     = (const float*)d_in[6];
    const float* fc1_b     = (const float*)d_in[7];
    const float* fc2_w     = (const float*)d_in[8];
    const float* fc2_b     = (const float*)d_in[9];
    float* out = (float*)d_out;
    (void)in_sizes; (void)n_in; (void)out_size;

    reset_flags_kernel<<<4, 512>>>();
    pipeline_kernel<<<7, G3>>>(x, W_ih0, W_ih_rest, W_hh, b_ih, b_hh);
    fc_kernel<<<T_STEPS, HID>>>(fc1_w, fc1_b, fc2_w, fc2_b, out);
}

// round 3
// speedup vs baseline: 2.1318x; 1.1732x over previous
#include <cuda_runtime.h>
#include <cuda_bf16.h>
#include <cstdint>

// ---------------------------------------------------------------------------
// Batch-1 GRU (only batch element 1023 feeds the head), T=512, H=128, 4 layers.
// Wavefront pipeline, one persistent kernel, 20 CTAs:
//   role 0..3   : rec CTA for layer l=role (W_hh rows in registers)
//   role 4..15  : gi CTAs, layer l=1..3 x 4 t-phases (W_ih rows in registers)
//   role 16..19 : FC head CTAs, 4 t-phases
// Handoff via L2 with acquire/release flags, one 128B line per flag.
// ---------------------------------------------------------------------------

#define T_STEPS 512
#define HID 128
#define G3   384
#define FPAD 32   // ints per flag -> 128B line each

__device__ float g_H[4 * T_STEPS * HID];
__device__ float g_GI[3 * T_STEPS * G3];
__device__ int   f_h[4 * T_STEPS * FPAD];
__device__ int   f_gi[4 * T_STEPS * FPAD];

static __device__ __forceinline__ int fh_idx(int l, int t) { return (l * T_STEPS + t) * FPAD; }
static __device__ __forceinline__ int fg_idx(int l, int t) { return (l * T_STEPS + t) * FPAD; }

static __device__ __forceinline__ float fast_sigmoid(float x) {
    return __fdividef(1.0f, 1.0f + __expf(-x));
}
static __device__ __forceinline__ float fast_tanh(float x) {
    float e = __expf(2.0f * x);
    return 1.0f - __fdividef(2.0f, e + 1.0f);
}
static __device__ __forceinline__ float f32x2_lo(unsigned long long v) {
    return __uint_as_float((unsigned int)(v & 0xffffffffu));
}
static __device__ __forceinline__ float f32x2_hi(unsigned long long v) {
    return __uint_as_float((unsigned int)(v >> 32));
}
static __device__ __forceinline__ void st_release(int* p, int v) {
    asm volatile("st.release.gpu.global.s32 [%0], %1;" :: "l"(p), "r"(v) : "memory");
}
static __device__ __forceinline__ int ld_acquire(const int* p) {
    int v;
    asm volatile("ld.acquire.gpu.global.s32 %0, [%1];" : "=r"(v) : "l"(p) : "memory");
    return v;
}
static __device__ __forceinline__ void spin_until(const int* p) {
    while (ld_acquire(p) == 0) { }
}

static __device__ __forceinline__ float dot128(const unsigned long long* w,
                                               const float* sh_vec) {
    unsigned long long a0 = 0ull, a1 = 0ull, a2 = 0ull, a3 = 0ull;
    const ulonglong2* h2 = reinterpret_cast<const ulonglong2*>(sh_vec);
#pragma unroll
    for (int kk = 0; kk < 16; kk++) {
        ulonglong2 hv0 = h2[2 * kk];
        ulonglong2 hv1 = h2[2 * kk + 1];
        asm("fma.rn.f32x2 %0, %1, %2, %0;" : "+l"(a0) : "l"(w[4 * kk + 0]), "l"(hv0.x));
        asm("fma.rn.f32x2 %0, %1, %2, %0;" : "+l"(a1) : "l"(w[4 * kk + 1]), "l"(hv0.y));
        asm("fma.rn.f32x2 %0, %1, %2, %0;" : "+l"(a2) : "l"(w[4 * kk + 2]), "l"(hv1.x));
        asm("fma.rn.f32x2 %0, %1, %2, %0;" : "+l"(a3) : "l"(w[4 * kk + 3]), "l"(hv1.y));
    }
    unsigned long long s01, s23, s;
    asm("add.rn.f32x2 %0, %1, %2;" : "=l"(s01) : "l"(a0), "l"(a1));
    asm("add.rn.f32x2 %0, %1, %2;" : "=l"(s23) : "l"(a2), "l"(a3));
    asm("add.rn.f32x2 %0, %1, %2;" : "=l"(s)   : "l"(s01), "l"(s23));
    return f32x2_lo(s) + f32x2_hi(s);
}

static __device__ __forceinline__ void load_row128(unsigned long long* w,
                                                   const float* row) {
    const ulonglong2* wr = reinterpret_cast<const ulonglong2*>(row);
#pragma unroll
    for (int kk = 0; kk < 32; kk++) {
        ulonglong2 v = wr[kk];
        w[2 * kk]     = v.x;
        w[2 * kk + 1] = v.y;
    }
}

__global__ void reset_flags_kernel() {
    int i = blockIdx.x * blockDim.x + threadIdx.x;
    if (i < 4 * T_STEPS) { f_h[i * FPAD] = 0; f_gi[i * FPAD] = 0; }
}

// ---------------------------------------------------------------------------
__global__ void __launch_bounds__(G3, 1)
pipeline_kernel(const float* __restrict__ x,         // (512,2,1024)
                const float* __restrict__ W_ih0,     // (384,2)
                const float* __restrict__ W_ih_rest, // (3,384,128)
                const float* __restrict__ W_hh,      // (4,384,128)
                const float* __restrict__ b_ih,      // (4,384)
                const float* __restrict__ b_hh,      // (4,384)
                const float* __restrict__ fc1_w,     // (128,128)
                const float* __restrict__ fc1_b,     // (128)
                const float* __restrict__ fc2_w,     // (3,128)
                const float* __restrict__ fc2_b,     // (3)
                float* __restrict__ out)             // (512,3)
{
    const int role = blockIdx.x;
    const int j = threadIdx.x;

    if (role < 4) {
        // ================= rec CTA, layer l = role =========================
        const int l = role;
        __shared__ __align__(16) float sh_h[HID];
        __shared__ float sh_gh[G3];
        __shared__ float sh_gi[2][G3];

        unsigned long long w[64];
        load_row128(w, W_hh + ((size_t)l * G3 + j) * HID);
        const float bh = b_hh[l * G3 + j];

        float w0 = 0.f, w1 = 0.f, bi0 = 0.f;
        if (l == 0) { w0 = W_ih0[j * 2]; w1 = W_ih0[j * 2 + 1]; bi0 = b_ih[j]; }
        const float* gi_in = (l > 0) ? (g_GI + (size_t)(l - 1) * T_STEPS * G3) : nullptr;
        float* h_out = g_H + (size_t)l * T_STEPS * HID;

        // preamble: zero h, stage gi(0)
        if (j < HID) sh_h[j] = 0.0f;
        if (l > 0 && j == 383) spin_until(&f_gi[fg_idx(l, 0)]);
        __syncthreads();
        {
            float g0;
            if (l == 0) {
                float x0 = __ldg(x + 1023);
                float x1 = __ldg(x + 2047);
                g0 = fmaf(w0, x0, fmaf(w1, x1, bi0));
            } else {
                g0 = gi_in[j];
            }
            sh_gi[0][j] = g0;
        }
        __syncthreads();

        for (int t = 0; t < T_STEPS; t++) {
            const int cur = t & 1, nxt = cur ^ 1;

            // non-blocking pre-check of gi flag for t+1 (latency overlaps dot)
            int ready = 1;
            if (l > 0 && j == 383 && t + 1 < T_STEPS)
                ready = ld_acquire(&f_gi[fg_idx(l, t + 1)]);

            float s = dot128(w, sh_h);
            sh_gh[j] = s + bh;

            if (l > 0 && j == 383 && t + 1 < T_STEPS && !ready)
                spin_until(&f_gi[fg_idx(l, t + 1)]);
            __syncthreads();   // BAR1: gh ready; flag(t+1) acquired CTA-wide

            // prefetch gi(t+1) into the other smem buffer (hidden by gates)
            if (t + 1 < T_STEPS) {
                float gnext;
                if (l == 0) {
                    float x0 = __ldg(x + (size_t)(t + 1) * 2048 + 1023);
                    float x1 = __ldg(x + (size_t)(t + 1) * 2048 + 2047);
                    gnext = fmaf(w0, x0, fmaf(w1, x1, bi0));
                } else {
                    gnext = gi_in[(size_t)(t + 1) * G3 + j];
                }
                sh_gi[nxt][j] = gnext;
            }

            if (j < HID) {
                float ghr = sh_gh[j];
                float ghz = sh_gh[j + HID];
                float ghn = sh_gh[j + 2 * HID];
                float r = fast_sigmoid(sh_gi[cur][j] + ghr);
                float z = fast_sigmoid(sh_gi[cur][j + HID] + ghz);
                float n = fast_tanh(fmaf(r, ghn, sh_gi[cur][j + 2 * HID]));
                float hnew = fmaf(z, sh_h[j] - n, n);
                sh_h[j] = hnew;               // safe: all sh_h reads were pre-BAR1
                h_out[t * HID + j] = hnew;
            }
            __syncthreads();   // BAR2: new h + gi(t+1) staged
            if (j == 0) st_release(&f_h[fh_idx(l, t)], 1);
        }
    } else if (role < 16) {
        // ================= gi CTA: layer l, phase ==========================
        const int idx = role - 4;
        const int l = idx / 4 + 1;          // 1..3
        const int phase = idx % 4;
        __shared__ __align__(16) float sh_h[HID];

        unsigned long long w[64];
        load_row128(w, W_ih_rest + ((size_t)(l - 1) * G3 + j) * HID);
        const float bi = b_ih[l * G3 + j];
        float* gi_out = g_GI + (size_t)(l - 1) * T_STEPS * G3;
        const float* h_in = g_H + (size_t)(l - 1) * T_STEPS * HID;

        for (int t = phase; t < T_STEPS; t += 4) {
            if (j == 0) spin_until(&f_h[fh_idx(l - 1, t)]);
            __syncthreads();
            if (j < 32) {
                reinterpret_cast<float4*>(sh_h)[j] =
                    reinterpret_cast<const float4*>(h_in + t * HID)[j];
            }
            __syncthreads();
            gi_out[(size_t)t * G3 + j] = dot128(w, sh_h) + bi;
            __syncthreads();
            if (j == 0) st_release(&f_gi[fg_idx(l, t)], 1);
        }
    } else {
        // ================= FC head CTA: phase ==============================
        const int phase = role - 16;
        __shared__ __align__(16) float sh_h[HID];
        __shared__ float sh_hid[HID];

        unsigned long long w[64];
        float b1 = 0.f;
        if (j < HID) {
            load_row128(w, fc1_w + (size_t)j * HID);
            b1 = fc1_b[j];
        }
        const float* h_in = g_H + (size_t)3 * T_STEPS * HID;

        for (int t = phase; t < T_STEPS; t += 4) {
            if (j == 0) spin_until(&f_h[fh_idx(3, t)]);
            __syncthreads();
            if (j < 32) {
                reinterpret_cast<float4*>(sh_h)[j] =
                    reinterpret_cast<const float4*>(h_in + t * HID)[j];
            }
            __syncthreads();
            if (j < HID) {
                sh_hid[j] = fmaxf(dot128(w, sh_h) + b1, 0.0f);
            }
            __syncthreads();
            if (j < 96) {
                int i = j >> 5;          // output row 0..2
                int lane = j & 31;
                float p = 0.f;
#pragma unroll
                for (int k = 0; k < 4; k++) {
                    int c = lane + 32 * k;
                    p = fmaf(__ldg(fc2_w + i * HID + c), sh_hid[c], p);
                }
#pragma unroll
                for (int off = 16; off > 0; off >>= 1)
                    p += __shfl_down_sync(0xffffffffu, p, off);
                if (lane == 0) out[t * 3 + i] = p + __ldg(fc2_b + i);
            }
            __syncthreads();
        }
    }
}

// ---------------------------------------------------------------------------
extern "C" void kernel_launch(void* const* d_in, const int* in_sizes, int n_in,
                              void* d_out, int out_size) {
    const float* x         = (const float*)d_in[0];
    const float* W_ih0     = (const float*)d_in[1];
    const float* W_ih_rest = (const float*)d_in[2];
    const float* W_hh      = (const float*)d_in[3];
    const float* b_ih      = (const float*)d_in[4];
    const float* b_hh      = (const float*)d_in[5];
    const float* fc1_w     = (const float*)d_in[6];
    const float* fc1_b     = (const float*)d_in[7];
    const float* fc2_w     = (const float*)d_in[8];
    const float* fc2_b     = (const float*)d_in[9];
    float* out = (float*)d_out;
    (void)in_sizes; (void)n_in; (void)out_size;

    reset_flags_kernel<<<8, 512>>>();
    pipeline_kernel<<<20, G3>>>(x, W_ih0, W_ih_rest, W_hh, b_ih, b_hh,
                                fc1_w, fc1_b, fc2_w, fc2_b, out);
}

// round 4
// speedup vs baseline: 2.4094x; 1.1302x over previous
#include <cuda_runtime.h>
#include <cuda_bf16.h>
#include <cstdint>

// ---------------------------------------------------------------------------
// Batch-1 GRU (only batch element 1023 feeds the head), T=512, H=128, 4 layers.
// Wavefront pipeline, one persistent kernel, 20 CTAs:
//   role 0..3   : rec CTA for layer l=role (W_hh rows in registers)
//   role 4..15  : gi CTAs, layer l=1..3 x 4 t-phases (W_ih rows in registers)
//   role 16..19 : FC head CTAs, 4 t-phases
// Handoff via L2 with acquire/release flags, one 128B line per flag.
// ---------------------------------------------------------------------------

#define T_STEPS 512
#define HID 128
#define G3   384
#define FPAD 32   // ints per flag -> 128B line each

__device__ float g_H[4 * T_STEPS * HID];
__device__ float g_GI[3 * T_STEPS * G3];
__device__ int   f_h[4 * T_STEPS * FPAD];
__device__ int   f_gi[4 * T_STEPS * FPAD];

static __device__ __forceinline__ int fh_idx(int l, int t) { return (l * T_STEPS + t) * FPAD; }
static __device__ __forceinline__ int fg_idx(int l, int t) { return (l * T_STEPS + t) * FPAD; }

static __device__ __forceinline__ float fast_sigmoid(float x) {
    return __fdividef(1.0f, 1.0f + __expf(-x));
}
static __device__ __forceinline__ float fast_tanh(float x) {
    float e = __expf(2.0f * x);
    return 1.0f - __fdividef(2.0f, e + 1.0f);
}
static __device__ __forceinline__ float f32x2_lo(unsigned long long v) {
    return __uint_as_float((unsigned int)(v & 0xffffffffu));
}
static __device__ __forceinline__ float f32x2_hi(unsigned long long v) {
    return __uint_as_float((unsigned int)(v >> 32));
}
static __device__ __forceinline__ void st_release(int* p, int v) {
    asm volatile("st.release.gpu.global.s32 [%0], %1;" :: "l"(p), "r"(v) : "memory");
}
static __device__ __forceinline__ int ld_acquire(const int* p) {
    int v;
    asm volatile("ld.acquire.gpu.global.s32 %0, [%1];" : "=r"(v) : "l"(p) : "memory");
    return v;
}
static __device__ __forceinline__ void spin_until(const int* p) {
    while (ld_acquire(p) == 0) { }
}

static __device__ __forceinline__ float dot128(const unsigned long long* w,
                                               const float* sh_vec) {
    unsigned long long a0 = 0ull, a1 = 0ull, a2 = 0ull, a3 = 0ull;
    const ulonglong2* h2 = reinterpret_cast<const ulonglong2*>(sh_vec);
#pragma unroll
    for (int kk = 0; kk < 16; kk++) {
        ulonglong2 hv0 = h2[2 * kk];
        ulonglong2 hv1 = h2[2 * kk + 1];
        asm("fma.rn.f32x2 %0, %1, %2, %0;" : "+l"(a0) : "l"(w[4 * kk + 0]), "l"(hv0.x));
        asm("fma.rn.f32x2 %0, %1, %2, %0;" : "+l"(a1) : "l"(w[4 * kk + 1]), "l"(hv0.y));
        asm("fma.rn.f32x2 %0, %1, %2, %0;" : "+l"(a2) : "l"(w[4 * kk + 2]), "l"(hv1.x));
        asm("fma.rn.f32x2 %0, %1, %2, %0;" : "+l"(a3) : "l"(w[4 * kk + 3]), "l"(hv1.y));
    }
    unsigned long long s01, s23, s;
    asm("add.rn.f32x2 %0, %1, %2;" : "=l"(s01) : "l"(a0), "l"(a1));
    asm("add.rn.f32x2 %0, %1, %2;" : "=l"(s23) : "l"(a2), "l"(a3));
    asm("add.rn.f32x2 %0, %1, %2;" : "=l"(s)   : "l"(s01), "l"(s23));
    return f32x2_lo(s) + f32x2_hi(s);
}

static __device__ __forceinline__ void load_row128(unsigned long long* w,
                                                   const float* row) {
    const ulonglong2* wr = reinterpret_cast<const ulonglong2*>(row);
#pragma unroll
    for (int kk = 0; kk < 32; kk++) {
        ulonglong2 v = wr[kk];
        w[2 * kk]     = v.x;
        w[2 * kk + 1] = v.y;
    }
}

__global__ void reset_flags_kernel() {
    int i = blockIdx.x * blockDim.x + threadIdx.x;
    if (i < 4 * T_STEPS) { f_h[i * FPAD] = 0; f_gi[i * FPAD] = 0; }
}

// ---------------------------------------------------------------------------
__global__ void __launch_bounds__(G3, 1)
pipeline_kernel(const float* __restrict__ x,         // (512,2,1024)
                const float* __restrict__ W_ih0,     // (384,2)
                const float* __restrict__ W_ih_rest, // (3,384,128)
                const float* __restrict__ W_hh,      // (4,384,128)
                const float* __restrict__ b_ih,      // (4,384)
                const float* __restrict__ b_hh,      // (4,384)
                const float* __restrict__ fc1_w,     // (128,128)
                const float* __restrict__ fc1_b,     // (128)
                const float* __restrict__ fc2_w,     // (3,128)
                const float* __restrict__ fc2_b,     // (3)
                float* __restrict__ out)             // (512,3)
{
    const int role = blockIdx.x;
    const int j = threadIdx.x;

    if (role < 4) {
        // ================= rec CTA, layer l = role =========================
        const int l = role;
        __shared__ __align__(16) float sh_h[HID];
        __shared__ float sh_gh[G3];
        __shared__ float sh_gi[2][G3];

        unsigned long long w[64];
        load_row128(w, W_hh + ((size_t)l * G3 + j) * HID);
        const float bh = b_hh[l * G3 + j];

        float w0 = 0.f, w1 = 0.f, bi0 = 0.f;
        if (l == 0) { w0 = W_ih0[j * 2]; w1 = W_ih0[j * 2 + 1]; bi0 = b_ih[j]; }
        const float* gi_in = (l > 0) ? (g_GI + (size_t)(l - 1) * T_STEPS * G3) : nullptr;
        float* h_out = g_H + (size_t)l * T_STEPS * HID;

        // preamble: zero h, stage gi(0)
        if (j < HID) sh_h[j] = 0.0f;
        if (l > 0 && j == 383) spin_until(&f_gi[fg_idx(l, 0)]);
        __syncthreads();
        {
            float g0;
            if (l == 0) {
                float x0 = __ldg(x + 1023);
                float x1 = __ldg(x + 2047);
                g0 = fmaf(w0, x0, fmaf(w1, x1, bi0));
            } else {
                g0 = gi_in[j];
            }
            sh_gi[0][j] = g0;
        }
        __syncthreads();

        for (int t = 0; t < T_STEPS; t++) {
            const int cur = t & 1, nxt = cur ^ 1;

            // non-blocking pre-check of gi flag for t+1 (latency overlaps dot)
            int ready = 1;
            if (l > 0 && j == 383 && t + 1 < T_STEPS)
                ready = ld_acquire(&f_gi[fg_idx(l, t + 1)]);

            float s = dot128(w, sh_h);
            sh_gh[j] = s + bh;

            if (l > 0 && j == 383 && t + 1 < T_STEPS && !ready)
                spin_until(&f_gi[fg_idx(l, t + 1)]);
            __syncthreads();   // BAR1: gh ready; flag(t+1) acquired CTA-wide

            // prefetch gi(t+1) into the other smem buffer (hidden by gates)
            if (t + 1 < T_STEPS) {
                float gnext;
                if (l == 0) {
                    float x0 = __ldg(x + (size_t)(t + 1) * 2048 + 1023);
                    float x1 = __ldg(x + (size_t)(t + 1) * 2048 + 2047);
                    gnext = fmaf(w0, x0, fmaf(w1, x1, bi0));
                } else {
                    gnext = gi_in[(size_t)(t + 1) * G3 + j];
                }
                sh_gi[nxt][j] = gnext;
            }

            if (j < HID) {
                float ghr = sh_gh[j];
                float ghz = sh_gh[j + HID];
                float ghn = sh_gh[j + 2 * HID];
                float r = fast_sigmoid(sh_gi[cur][j] + ghr);
                float z = fast_sigmoid(sh_gi[cur][j + HID] + ghz);
                float n = fast_tanh(fmaf(r, ghn, sh_gi[cur][j + 2 * HID]));
                float hnew = fmaf(z, sh_h[j] - n, n);
                sh_h[j] = hnew;               // safe: all sh_h reads were pre-BAR1
                h_out[t * HID + j] = hnew;
            }
            __syncthreads();   // BAR2: new h + gi(t+1) staged
            if (j == 0) st_release(&f_h[fh_idx(l, t)], 1);
        }
    } else if (role < 16) {
        // ================= gi CTA: layer l, phase ==========================
        const int idx = role - 4;
        const int l = idx / 4 + 1;          // 1..3
        const int phase = idx % 4;
        __shared__ __align__(16) float sh_h[HID];

        unsigned long long w[64];
        load_row128(w, W_ih_rest + ((size_t)(l - 1) * G3 + j) * HID);
        const float bi = b_ih[l * G3 + j];
        float* gi_out = g_GI + (size_t)(l - 1) * T_STEPS * G3;
        const float* h_in = g_H + (size_t)(l - 1) * T_STEPS * HID;

        for (int t = phase; t < T_STEPS; t += 4) {
            if (j == 0) spin_until(&f_h[fh_idx(l - 1, t)]);
            __syncthreads();
            if (j < 32) {
                reinterpret_cast<float4*>(sh_h)[j] =
                    reinterpret_cast<const float4*>(h_in + t * HID)[j];
            }
            __syncthreads();
            gi_out[(size_t)t * G3 + j] = dot128(w, sh_h) + bi;
            __syncthreads();
            if (j == 0) st_release(&f_gi[fg_idx(l, t)], 1);
        }
    } else {
        // ================= FC head CTA: phase ==============================
        const int phase = role - 16;
        __shared__ __align__(16) float sh_h[HID];
        __shared__ float sh_hid[HID];

        unsigned long long w[64];
        float b1 = 0.f;
        if (j < HID) {
            load_row128(w, fc1_w + (size_t)j * HID);
            b1 = fc1_b[j];
        }
        const float* h_in = g_H + (size_t)3 * T_STEPS * HID;

        for (int t = phase; t < T_STEPS; t += 4) {
            if (j == 0) spin_until(&f_h[fh_idx(3, t)]);
            __syncthreads();
            if (j < 32) {
                reinterpret_cast<float4*>(sh_h)[j] =
                    reinterpret_cast<const float4*>(h_in + t * HID)[j];
            }
            __syncthreads();
            if (j < HID) {
                sh_hid[j] = fmaxf(dot128(w, sh_h) + b1, 0.0f);
            }
            __syncthreads();
            if (j < 96) {
                int i = j >> 5;          // output row 0..2
                int lane = j & 31;
                float p = 0.f;
#pragma unroll
                for (int k = 0; k < 4; k++) {
                    int c = lane + 32 * k;
                    p = fmaf(__ldg(fc2_w + i * HID + c), sh_hid[c], p);
                }
#pragma unroll
                for (int off = 16; off > 0; off >>= 1)
                    p += __shfl_down_sync(0xffffffffu, p, off);
                if (lane == 0) out[t * 3 + i] = p + __ldg(fc2_b + i);
            }
            __syncthreads();
        }
    }
}

// ---------------------------------------------------------------------------
extern "C" void kernel_launch(void* const* d_in, const int* in_sizes, int n_in,
                              void* d_out, int out_size) {
    const float* x         = (const float*)d_in[0];
    const float* W_ih0     = (const float*)d_in[1];
    const float* W_ih_rest = (const float*)d_in[2];
    const float* W_hh      = (const float*)d_in[3];
    const float* b_ih      = (const float*)d_in[4];
    const float* b_hh      = (const float*)d_in[5];
    const float* fc1_w     = (const float*)d_in[6];
    const float* fc1_b     = (const float*)d_in[7];
    const float* fc2_w     = (const float*)d_in[8];
    const float* fc2_b     = (const float*)d_in[9];
    float* out = (float*)d_out;
    (void)in_sizes; (void)n_in; (void)out_size;

    reset_flags_kernel<<<8, 512>>>();
    pipeline_kernel<<<20, G3>>>(x, W_ih0, W_ih_rest, W_hh, b_ih, b_hh,
                                fc1_w, fc1_b, fc2_w, fc2_b, out);
}